// round 16
// baseline (speedup 1.0000x reference)
#include <cuda_runtime.h>
#include <cuda_fp16.h>
#include <cstdint>
#include <math.h>

#define HW    4096
#define CDIM  684
#define NP    512
#define BS    16
#define KPAD  832            // 684 channels + 121 taps + 27 zero pad
#define NCHUNK 26            // K chunks of 32
#define TAPPAD 148

// smem stage layout (bytes), K-chunk = 32 (R9 config)
#define A_ROW_B   80         // 32 halves (64B) + 16B pad
#define B_ROW_B   272        // 128 halves (256B) + 16B pad
#define A_STAGE_B (128 * A_ROW_B)            // 10240
#define B_STAGE_B (32 * B_ROW_B)             // 8704
#define STAGE_B   (A_STAGE_B + B_STAGE_B)    // 18944
#define NSTAGES   4

// -------- device scratch --------
__device__ float  g_beta[BS * HW];                   // 256 KB, L2-resident
__device__ __half g_Ah  [NP * KPAD];
__device__ __half g_Bh  [(size_t)BS * KPAD * HW];    // 109 MB
__device__ float  g_qe  [BS * NP];
__device__ float  g_epart[4][BS * HW];
__device__ float  g_e   [BS * HW];
__device__ float  g_ps  [BS * 32];
__device__ float  g_S   [BS];

__device__ __forceinline__ uint32_t smem_u32(const void* p) {
    uint32_t a;
    asm("{ .reg .u64 t; cvta.to.shared.u64 t, %1; cvt.u32.u64 %0, t; }" : "=r"(a) : "l"(p));
    return a;
}

// ================= prep kernels =================

// launch 0: beta = sum of 4 alpha maps
__global__ void beta_kernel(const float* __restrict__ alpha) {
    int idx = blockIdx.x * blockDim.x + threadIdx.x;
    if (idx < BS * HW) {
        int b = idx >> 12, n = idx & (HW - 1);
        const float* a = alpha + (size_t)b * 4 * HW + n;
        g_beta[idx] = a[0] + a[HW] + a[2 * HW] + a[3 * HW];
    }
}

// launch 1: build ALL rows of g_Bh in one pass.
__global__ void buildB_kernel(const float* __restrict__ x) {
    const int b = blockIdx.y;
    const int r = blockIdx.x >> 2;
    const int pix0 = (blockIdx.x & 3) * 1024 + threadIdx.x * 4;
    __half2* dst = (__half2*)(g_Bh + ((size_t)b * KPAD + r) * HW + pix0);
    if (r < CDIM) {
        float4 v = *(const float4*)(x + ((size_t)b * CDIM + r) * HW + pix0);
        dst[0] = __floats2half2_rn(v.x, v.y);
        dst[1] = __floats2half2_rn(v.z, v.w);
    } else {
        const int t = r - CDIM;
        float v[4] = {0.f, 0.f, 0.f, 0.f};
        if (t < 121) {
            const int dy = t / 11, dx = t - dy * 11;
            const int y = (pix0 >> 7) + dy - 5;
            if (y >= 0 && y < 32) {
                const float* br = g_beta + b * HW + y * 128;
#pragma unroll
                for (int j = 0; j < 4; j++) {
                    const int xx = ((pix0 + j) & 127) + dx - 5;
                    if (xx >= 0 && xx < 128) v[j] = br[xx];
                }
            }
        }
        dst[0] = __floats2half2_rn(v[0], v[1]);
        dst[1] = __floats2half2_rn(v[2], v[3]);
    }
}

// launch 2: weights + query prep
__global__ void prep_kernel(const float* __restrict__ ua,
                            const float* __restrict__ ufw, const float* __restrict__ cqw,
                            const float* __restrict__ st_hat, const float* __restrict__ waw,
                            const float* __restrict__ wab, const float* __restrict__ uab,
                            const float* __restrict__ ufb, const float* __restrict__ cqb) {
    const int bx = blockIdx.x, tid = threadIdx.x;
    if (bx < NP) {
        const int p = bx;
        for (int c = tid; c < CDIM; c += 128)
            g_Ah[p * KPAD + c] = __float2half_rn(ua[p * CDIM + c]);
        for (int t = tid; t < TAPPAD; t += 128) {
            float s = 0.f;
            if (t < 121) {
                const float* ufp = ufw + p * 256;
                for (int q = 0; q < 256; q++)
                    s = fmaf(ufp[q], cqw[q * 121 + t], s);
            }
            g_Ah[p * KPAD + CDIM + t] = __float2half_rn(s);
        }
    } else {
        const int w = (bx - NP) * 4 + (tid >> 5);
        const int lane = tid & 31;
        const int b = w >> 9, p = w & (NP - 1);
        float s = 0.f;
        for (int i = lane; i < 256; i += 32) {
            s = fmaf(st_hat[b * 256 + i], waw[p * 256 + i], s);
            s = fmaf(ufw[p * 256 + i], cqb[i], s);
        }
#pragma unroll
        for (int o = 16; o > 0; o >>= 1) s += __shfl_down_sync(0xFFFFFFFFu, s, o);
        if (lane == 0) g_qe[w] = s + wab[p] + uab[p] + ufb[p];
    }
}

// ================= fp16 mma score kernel (launch 3 — profiled) =================
// grid x = (tile<<2)|pz  → the 4 pz CTAs sharing one B tile are wave-adjacent (L2 reuse).
__global__ __launch_bounds__(256, 2)
void score_kernel(const float* __restrict__ vaw) {
    extern __shared__ char smem[];
    __shared__ float qe_s[128], va_s[128];
    __shared__ float red[4][128];

    const int tid = threadIdx.x;
    const int wid = tid >> 5, lane = tid & 31;
    const int warp_m = wid & 3, warp_n = wid >> 2;
    const int g = lane >> 2, ti = lane & 3;
    const int b = blockIdx.y;
    const int tileY = blockIdx.x >> 2, pz = blockIdx.x & 3;
    const int pixbase = tileY * 128;

    const uint32_t sbase = smem_u32(smem);

    if (tid < 128) {
        qe_s[tid] = g_qe[b * NP + pz * 128 + tid];
        va_s[tid] = vaw[pz * 128 + tid];
    }

    const int ar0 = tid >> 2,          ag0 = tid & 3;
    const int ar1 = (tid + 256) >> 2,  ag1 = (tid + 256) & 3;
    const __half* Asrc0 = g_Ah + (size_t)(pz * 128 + ar0) * KPAD + ag0 * 8;
    const __half* Asrc1 = g_Ah + (size_t)(pz * 128 + ar1) * KPAD + ag1 * 8;
    const uint32_t Adst0 = ar0 * A_ROW_B + ag0 * 16;
    const uint32_t Adst1 = ar1 * A_ROW_B + ag1 * 16;
    const int br0 = tid >> 4,          bg0 = tid & 15;
    const int br1 = (tid + 256) >> 4,  bg1 = (tid + 256) & 15;
    const __half* Bsrc0 = g_Bh + ((size_t)b * KPAD + br0) * HW + pixbase + bg0 * 8;
    const __half* Bsrc1 = g_Bh + ((size_t)b * KPAD + br1) * HW + pixbase + bg1 * 8;
    const uint32_t Bdst0 = A_STAGE_B + br0 * B_ROW_B + bg0 * 16;
    const uint32_t Bdst1 = A_STAGE_B + br1 * B_ROW_B + bg1 * 16;

    auto issue = [&](int ch) {
        const uint32_t st = sbase + (ch & 3) * STAGE_B;
        const size_t ko = (size_t)ch * 32;
        asm volatile("cp.async.cg.shared.global [%0], [%1], 16;"
                     :: "r"(st + Adst0), "l"(Asrc0 + ko) : "memory");
        asm volatile("cp.async.cg.shared.global [%0], [%1], 16;"
                     :: "r"(st + Adst1), "l"(Asrc1 + ko) : "memory");
        asm volatile("cp.async.cg.shared.global [%0], [%1], 16;"
                     :: "r"(st + Bdst0), "l"(Bsrc0 + ko * HW) : "memory");
        asm volatile("cp.async.cg.shared.global [%0], [%1], 16;"
                     :: "r"(st + Bdst1), "l"(Bsrc1 + ko * HW) : "memory");
        asm volatile("cp.async.commit_group;" ::: "memory");
    };

    issue(0); issue(1); issue(2);

    const int mat = lane >> 3, mrow = lane & 7;
    const uint32_t aoff = (uint32_t)(warp_m * 32 + mrow + (mat & 1) * 8) * A_ROW_B + (mat >> 1) * 16;
    const uint32_t boff = A_STAGE_B + (uint32_t)(mrow + (mat & 1) * 8) * B_ROW_B
                        + (uint32_t)(warp_n * 64 + (mat >> 1) * 8) * 2;

    float acc[2][8][4];
#pragma unroll
    for (int t = 0; t < 2; t++)
#pragma unroll
        for (int u = 0; u < 8; u++)
#pragma unroll
            for (int c = 0; c < 4; c++) acc[t][u][c] = 0.f;

    for (int ch = 0; ch < NCHUNK; ch++) {
        asm volatile("cp.async.wait_group 2;" ::: "memory");
        __syncthreads();

        const uint32_t st = sbase + (ch & 3) * STAGE_B;
        if (ch + 3 < NCHUNK) issue(ch + 3);
        else asm volatile("cp.async.commit_group;" ::: "memory");

#pragma unroll
        for (int kh = 0; kh < 2; kh++) {
            uint32_t afr[2][4], bfr[4][4];
#pragma unroll
            for (int t = 0; t < 2; t++)
                asm volatile("ldmatrix.sync.aligned.m8n8.x4.shared.b16 {%0,%1,%2,%3}, [%4];"
                             : "=r"(afr[t][0]), "=r"(afr[t][1]), "=r"(afr[t][2]), "=r"(afr[t][3])
                             : "r"(st + aoff + t * 16 * A_ROW_B + kh * 32));
#pragma unroll
            for (int h = 0; h < 4; h++)
                asm volatile("ldmatrix.sync.aligned.m8n8.x4.trans.shared.b16 {%0,%1,%2,%3}, [%4];"
                             : "=r"(bfr[h][0]), "=r"(bfr[h][1]), "=r"(bfr[h][2]), "=r"(bfr[h][3])
                             : "r"(st + boff + kh * 16 * B_ROW_B + h * 32));
#pragma unroll
            for (int t = 0; t < 2; t++)
#pragma unroll
                for (int u = 0; u < 8; u++) {
                    const uint32_t b0 = bfr[u >> 1][(u & 1) * 2];
                    const uint32_t b1 = bfr[u >> 1][(u & 1) * 2 + 1];
                    asm volatile(
                        "mma.sync.aligned.m16n8k16.row.col.f32.f16.f16.f32 "
                        "{%0,%1,%2,%3}, {%4,%5,%6,%7}, {%8,%9}, {%0,%1,%2,%3};"
                        : "+f"(acc[t][u][0]), "+f"(acc[t][u][1]),
                          "+f"(acc[t][u][2]), "+f"(acc[t][u][3])
                        : "r"(afr[t][0]), "r"(afr[t][1]), "r"(afr[t][2]), "r"(afr[t][3]),
                          "r"(b0), "r"(b1));
                }
        }
    }

    // epilogue
    float part[8][2];
#pragma unroll
    for (int u = 0; u < 8; u++) { part[u][0] = 0.f; part[u][1] = 0.f; }
#pragma unroll
    for (int t = 0; t < 2; t++) {
        const int p0 = warp_m * 32 + t * 16 + g;
        const float q0 = qe_s[p0],     v0 = va_s[p0];
        const float q1 = qe_s[p0 + 8], v1 = va_s[p0 + 8];
#pragma unroll
        for (int u = 0; u < 8; u++) {
            part[u][0] = fmaf(v0, tanhf(acc[t][u][0] + q0), part[u][0]);
            part[u][1] = fmaf(v0, tanhf(acc[t][u][1] + q0), part[u][1]);
            part[u][0] = fmaf(v1, tanhf(acc[t][u][2] + q1), part[u][0]);
            part[u][1] = fmaf(v1, tanhf(acc[t][u][3] + q1), part[u][1]);
        }
    }
#pragma unroll
    for (int u = 0; u < 8; u++)
#pragma unroll
        for (int j = 0; j < 2; j++) {
            part[u][j] += __shfl_down_sync(0xFFFFFFFFu, part[u][j], 16);
            part[u][j] += __shfl_down_sync(0xFFFFFFFFu, part[u][j], 8);
            part[u][j] += __shfl_down_sync(0xFFFFFFFFu, part[u][j], 4);
        }
    if (lane < 4) {
#pragma unroll
        for (int u = 0; u < 8; u++)
#pragma unroll
            for (int j = 0; j < 2; j++)
                red[warp_m][warp_n * 64 + u * 8 + ti * 2 + j] = part[u][j];
    }
    __syncthreads();
    if (tid < 128) {
        float s = red[0][tid] + red[1][tid] + red[2][tid] + red[3][tid];
        g_epart[pz][b * HW + pixbase + tid] = s;
    }
}

// ================= softmax / outputs =================
__global__ void softmax1_kernel(const float* __restrict__ vab) {
    const int b = blockIdx.y, tile = blockIdx.x, tid = threadIdx.x;
    const int idx = b * HW + tile * 128 + tid;
    float v = expf(g_epart[0][idx] + g_epart[1][idx] +
                   g_epart[2][idx] + g_epart[3][idx] + vab[0]);
    g_e[idx] = v;
#pragma unroll
    for (int o = 16; o > 0; o >>= 1) v += __shfl_down_sync(0xFFFFFFFFu, v, o);
    __shared__ float red[4];
    if ((tid & 31) == 0) red[tid >> 5] = v;
    __syncthreads();
    if (tid == 0) g_ps[b * 32 + tile] = red[0] + red[1] + red[2] + red[3];
}

__global__ void softmax2_kernel() {
    const int b = blockIdx.x, lane = threadIdx.x;
    float v = g_ps[b * 32 + lane];
#pragma unroll
    for (int o = 16; o > 0; o >>= 1) v += __shfl_down_sync(0xFFFFFFFFu, v, o);
    if (lane == 0) g_S[b] = v + 1e-8f;
}

// fused alpha + context: blocks [0, BS*CDIM) do context rows; rest do alpha.
#define CTX_BLOCKS (BS * CDIM)
__global__ void outputs_kernel(float* __restrict__ out_ctx, float* __restrict__ out_alpha) {
    const int bx = blockIdx.x;
    if (bx < CTX_BLOCKS) {
        const int b = bx / CDIM, c = bx - b * CDIM;
        const __half2* xr = (const __half2*)(g_Bh + ((size_t)b * KPAD + c) * HW);
        const float* er = g_e + b * HW;
        float s = 0.f;
        for (int i = threadIdx.x; i < HW / 2; i += 128) {
            float2 xv = __half22float2(xr[i]);
            s = fmaf(xv.x, er[2 * i], s);
            s = fmaf(xv.y, er[2 * i + 1], s);
        }
        __shared__ float red[128];
        red[threadIdx.x] = s;
        __syncthreads();
        for (int st = 64; st > 0; st >>= 1) {
            if (threadIdx.x < st) red[threadIdx.x] += red[threadIdx.x + st];
            __syncthreads();
        }
        if (threadIdx.x == 0) out_ctx[b * CDIM + c] = red[0] / g_S[b];
    } else {
        const int base = (bx - CTX_BLOCKS) * 128 + threadIdx.x;   // 512 blocks x 128
        if (base < BS * HW) out_alpha[base] = g_e[base] / g_S[base >> 12];
    }
}

// ================= launch =================
extern "C" void kernel_launch(void* const* d_in, const int* in_sizes, int n_in,
                              void* d_out, int out_size) {
    const float* x        = (const float*)d_in[0];
    const float* st_hat   = (const float*)d_in[1];
    const float* alpha    = (const float*)d_in[2];
    const float* convQ_w  = (const float*)d_in[3];
    const float* convQ_b  = (const float*)d_in[4];
    const float* Wa_w     = (const float*)d_in[5];
    const float* Wa_b     = (const float*)d_in[6];
    const float* convUa_w = (const float*)d_in[7];
    const float* convUa_b = (const float*)d_in[8];
    const float* Uf_w     = (const float*)d_in[9];
    const float* Uf_b     = (const float*)d_in[10];
    const float* Va_w     = (const float*)d_in[11];
    const float* Va_b     = (const float*)d_in[12];

    float* out_ctx   = (float*)d_out;
    float* out_alpha = (float*)d_out + BS * CDIM;

    const int dyn_bytes = NSTAGES * STAGE_B;   // 75776
    cudaFuncSetAttribute(score_kernel, cudaFuncAttributeMaxDynamicSharedMemorySize,
                         dyn_bytes);

    beta_kernel<<<(BS * HW + 1023) / 1024, 1024>>>(alpha);                        // 0
    {   // launch 1
        dim3 g(KPAD * 4, BS);
        buildB_kernel<<<g, 256>>>(x);
    }
    // launch 2
    prep_kernel<<<NP + 2048, 128>>>(convUa_w, Uf_w, convQ_w, st_hat, Wa_w, Wa_b,
                                    convUa_b, Uf_b, convQ_b);
    {   // launch 3 (profiled): x = (tile<<2)|pz
        dim3 gs(128, BS);
        score_kernel<<<gs, 256, dyn_bytes>>>(Va_w);
    }
    {   // launch 4
        dim3 g(32, BS);
        softmax1_kernel<<<g, 128>>>(Va_b);
    }
    softmax2_kernel<<<BS, 32>>>();                                                // 5
    outputs_kernel<<<CTX_BLOCKS + 512, 128>>>(out_ctx, out_alpha);                // 6
}

// round 17
// speedup vs baseline: 1.0225x; 1.0225x over previous
#include <cuda_runtime.h>
#include <cuda_fp16.h>
#include <cstdint>
#include <math.h>

#define HW    4096
#define CDIM  684
#define NP    512
#define BS    16
#define KPAD  832            // 684 channels + 121 taps + 27 zero pad
#define NCHUNK 26            // K chunks of 32
#define TAPPAD 148

// smem stage layout (bytes), K-chunk = 32 (R9 config)
#define A_ROW_B   80         // 32 halves (64B) + 16B pad
#define B_ROW_B   272        // 128 halves (256B) + 16B pad
#define A_STAGE_B (128 * A_ROW_B)            // 10240
#define B_STAGE_B (32 * B_ROW_B)             // 8704
#define STAGE_B   (A_STAGE_B + B_STAGE_B)    // 18944
#define NSTAGES   4

// fused prep block ranges (grid.x)
#define BB_BLOCKS  (KPAD * 4)                // 3328: g_Bh rows (x-convert + taps)
#define AP_BLOCKS  NP                        // 512:  A-weight rows
#define QE_BLOCKS  ((BS * NP) / 8)           // 1024: qe, 8 warps/block
#define PREP_GX    (BB_BLOCKS + AP_BLOCKS + QE_BLOCKS)

// -------- device scratch --------
__device__ __half g_Ah  [NP * KPAD];
__device__ __half g_Bh  [(size_t)BS * KPAD * HW];    // 109 MB
__device__ float  g_qe  [BS * NP];
__device__ float  g_epart[4][BS * HW];
__device__ float  g_e   [BS * HW];
__device__ float  g_ps  [BS * 32];

__device__ __forceinline__ uint32_t smem_u32(const void* p) {
    uint32_t a;
    asm("{ .reg .u64 t; cvta.to.shared.u64 t, %1; cvt.u32.u64 %0, t; }" : "=r"(a) : "l"(p));
    return a;
}

// ================= fused prep kernel (launch 0) =================
// bx in [0, BB_BLOCKS): build g_Bh row r=bx>>2, segment bx&3, batch=by.
//   x rows: fp16 convert. tap rows: beta from 4 alpha reads (L2).
// bx in [BB, BB+AP): per-p A weights (copyUa + weff), by==0 only.
// bx in [BB+AP, ...): qe, 8 warps/block, by==0 only.
__global__ __launch_bounds__(256)
void prep_kernel(const float* __restrict__ x, const float* __restrict__ alpha,
                 const float* __restrict__ ua,
                 const float* __restrict__ ufw, const float* __restrict__ cqw,
                 const float* __restrict__ st_hat, const float* __restrict__ waw,
                 const float* __restrict__ wab, const float* __restrict__ uab,
                 const float* __restrict__ ufb, const float* __restrict__ cqb) {
    const int bx = blockIdx.x, by = blockIdx.y, tid = threadIdx.x;
    if (bx < BB_BLOCKS) {
        const int b = by;
        const int r = bx >> 2;
        const int pix0 = (bx & 3) * 1024 + tid * 4;
        __half2* dst = (__half2*)(g_Bh + ((size_t)b * KPAD + r) * HW + pix0);
        if (r < CDIM) {
            float4 v = *(const float4*)(x + ((size_t)b * CDIM + r) * HW + pix0);
            dst[0] = __floats2half2_rn(v.x, v.y);
            dst[1] = __floats2half2_rn(v.z, v.w);
        } else {
            const int t = r - CDIM;
            float v[4] = {0.f, 0.f, 0.f, 0.f};
            if (t < 121) {
                const int dy = t / 11, dx = t - dy * 11;
                const int y = (pix0 >> 7) + dy - 5;      // same row for all 4 px
                if (y >= 0 && y < 32) {
                    const float* a0 = alpha + (size_t)b * 4 * HW + y * 128;
#pragma unroll
                    for (int j = 0; j < 4; j++) {
                        const int xx = ((pix0 + j) & 127) + dx - 5;
                        if (xx >= 0 && xx < 128)
                            v[j] = a0[xx] + a0[HW + xx] + a0[2 * HW + xx] + a0[3 * HW + xx];
                    }
                }
            }
            dst[0] = __floats2half2_rn(v[0], v[1]);
            dst[1] = __floats2half2_rn(v[2], v[3]);
        }
    } else if (bx < BB_BLOCKS + AP_BLOCKS) {
        if (by != 0) return;
        const int p = bx - BB_BLOCKS;
        for (int c = tid; c < CDIM; c += 256)
            g_Ah[p * KPAD + c] = __float2half_rn(ua[p * CDIM + c]);
        if (tid < TAPPAD) {
            const int t = tid;
            float s = 0.f;
            if (t < 121) {
                const float* ufp = ufw + p * 256;
                for (int q = 0; q < 256; q++)
                    s = fmaf(ufp[q], cqw[q * 121 + t], s);
            }
            g_Ah[p * KPAD + CDIM + t] = __float2half_rn(s);
        }
    } else {
        if (by != 0) return;
        const int w = (bx - BB_BLOCKS - AP_BLOCKS) * 8 + (tid >> 5);  // 0..8191
        const int lane = tid & 31;
        const int b = w >> 9, p = w & (NP - 1);
        float s = 0.f;
        for (int i = lane; i < 256; i += 32) {
            s = fmaf(st_hat[b * 256 + i], waw[p * 256 + i], s);
            s = fmaf(ufw[p * 256 + i], cqb[i], s);
        }
#pragma unroll
        for (int o = 16; o > 0; o >>= 1) s += __shfl_down_sync(0xFFFFFFFFu, s, o);
        if (lane == 0) g_qe[w] = s + wab[p] + uab[p] + ufb[p];
    }
}

// ================= fp16 mma score kernel (launch 1) =================
// grid x = (tile<<2)|pz — the 4 pz CTAs sharing one B tile are wave-adjacent (L2 reuse).
__global__ __launch_bounds__(256, 2)
void score_kernel(const float* __restrict__ vaw) {
    extern __shared__ char smem[];
    __shared__ float qe_s[128], va_s[128];
    __shared__ float red[4][128];

    const int tid = threadIdx.x;
    const int wid = tid >> 5, lane = tid & 31;
    const int warp_m = wid & 3, warp_n = wid >> 2;
    const int g = lane >> 2, ti = lane & 3;
    const int b = blockIdx.y;
    const int tileY = blockIdx.x >> 2, pz = blockIdx.x & 3;
    const int pixbase = tileY * 128;

    const uint32_t sbase = smem_u32(smem);

    if (tid < 128) {
        qe_s[tid] = g_qe[b * NP + pz * 128 + tid];
        va_s[tid] = vaw[pz * 128 + tid];
    }

    const int ar0 = tid >> 2,          ag0 = tid & 3;
    const int ar1 = (tid + 256) >> 2,  ag1 = (tid + 256) & 3;
    const __half* Asrc0 = g_Ah + (size_t)(pz * 128 + ar0) * KPAD + ag0 * 8;
    const __half* Asrc1 = g_Ah + (size_t)(pz * 128 + ar1) * KPAD + ag1 * 8;
    const uint32_t Adst0 = ar0 * A_ROW_B + ag0 * 16;
    const uint32_t Adst1 = ar1 * A_ROW_B + ag1 * 16;
    const int br0 = tid >> 4,          bg0 = tid & 15;
    const int br1 = (tid + 256) >> 4,  bg1 = (tid + 256) & 15;
    const __half* Bsrc0 = g_Bh + ((size_t)b * KPAD + br0) * HW + pixbase + bg0 * 8;
    const __half* Bsrc1 = g_Bh + ((size_t)b * KPAD + br1) * HW + pixbase + bg1 * 8;
    const uint32_t Bdst0 = A_STAGE_B + br0 * B_ROW_B + bg0 * 16;
    const uint32_t Bdst1 = A_STAGE_B + br1 * B_ROW_B + bg1 * 16;

    auto issue = [&](int ch) {
        const uint32_t st = sbase + (ch & 3) * STAGE_B;
        const size_t ko = (size_t)ch * 32;
        asm volatile("cp.async.cg.shared.global [%0], [%1], 16;"
                     :: "r"(st + Adst0), "l"(Asrc0 + ko) : "memory");
        asm volatile("cp.async.cg.shared.global [%0], [%1], 16;"
                     :: "r"(st + Adst1), "l"(Asrc1 + ko) : "memory");
        asm volatile("cp.async.cg.shared.global [%0], [%1], 16;"
                     :: "r"(st + Bdst0), "l"(Bsrc0 + ko * HW) : "memory");
        asm volatile("cp.async.cg.shared.global [%0], [%1], 16;"
                     :: "r"(st + Bdst1), "l"(Bsrc1 + ko * HW) : "memory");
        asm volatile("cp.async.commit_group;" ::: "memory");
    };

    issue(0); issue(1); issue(2);

    const int mat = lane >> 3, mrow = lane & 7;
    const uint32_t aoff = (uint32_t)(warp_m * 32 + mrow + (mat & 1) * 8) * A_ROW_B + (mat >> 1) * 16;
    const uint32_t boff = A_STAGE_B + (uint32_t)(mrow + (mat & 1) * 8) * B_ROW_B
                        + (uint32_t)(warp_n * 64 + (mat >> 1) * 8) * 2;

    float acc[2][8][4];
#pragma unroll
    for (int t = 0; t < 2; t++)
#pragma unroll
        for (int u = 0; u < 8; u++)
#pragma unroll
            for (int c = 0; c < 4; c++) acc[t][u][c] = 0.f;

    for (int ch = 0; ch < NCHUNK; ch++) {
        asm volatile("cp.async.wait_group 2;" ::: "memory");
        __syncthreads();

        const uint32_t st = sbase + (ch & 3) * STAGE_B;
        if (ch + 3 < NCHUNK) issue(ch + 3);
        else asm volatile("cp.async.commit_group;" ::: "memory");

#pragma unroll
        for (int kh = 0; kh < 2; kh++) {
            uint32_t afr[2][4], bfr[4][4];
#pragma unroll
            for (int t = 0; t < 2; t++)
                asm volatile("ldmatrix.sync.aligned.m8n8.x4.shared.b16 {%0,%1,%2,%3}, [%4];"
                             : "=r"(afr[t][0]), "=r"(afr[t][1]), "=r"(afr[t][2]), "=r"(afr[t][3])
                             : "r"(st + aoff + t * 16 * A_ROW_B + kh * 32));
#pragma unroll
            for (int h = 0; h < 4; h++)
                asm volatile("ldmatrix.sync.aligned.m8n8.x4.trans.shared.b16 {%0,%1,%2,%3}, [%4];"
                             : "=r"(bfr[h][0]), "=r"(bfr[h][1]), "=r"(bfr[h][2]), "=r"(bfr[h][3])
                             : "r"(st + boff + kh * 16 * B_ROW_B + h * 32));
#pragma unroll
            for (int t = 0; t < 2; t++)
#pragma unroll
                for (int u = 0; u < 8; u++) {
                    const uint32_t b0 = bfr[u >> 1][(u & 1) * 2];
                    const uint32_t b1 = bfr[u >> 1][(u & 1) * 2 + 1];
                    asm volatile(
                        "mma.sync.aligned.m16n8k16.row.col.f32.f16.f16.f32 "
                        "{%0,%1,%2,%3}, {%4,%5,%6,%7}, {%8,%9}, {%0,%1,%2,%3};"
                        : "+f"(acc[t][u][0]), "+f"(acc[t][u][1]),
                          "+f"(acc[t][u][2]), "+f"(acc[t][u][3])
                        : "r"(afr[t][0]), "r"(afr[t][1]), "r"(afr[t][2]), "r"(afr[t][3]),
                          "r"(b0), "r"(b1));
                }
        }
    }

    // epilogue
    float part[8][2];
#pragma unroll
    for (int u = 0; u < 8; u++) { part[u][0] = 0.f; part[u][1] = 0.f; }
#pragma unroll
    for (int t = 0; t < 2; t++) {
        const int p0 = warp_m * 32 + t * 16 + g;
        const float q0 = qe_s[p0],     v0 = va_s[p0];
        const float q1 = qe_s[p0 + 8], v1 = va_s[p0 + 8];
#pragma unroll
        for (int u = 0; u < 8; u++) {
            part[u][0] = fmaf(v0, tanhf(acc[t][u][0] + q0), part[u][0]);
            part[u][1] = fmaf(v0, tanhf(acc[t][u][1] + q0), part[u][1]);
            part[u][0] = fmaf(v1, tanhf(acc[t][u][2] + q1), part[u][0]);
            part[u][1] = fmaf(v1, tanhf(acc[t][u][3] + q1), part[u][1]);
        }
    }
#pragma unroll
    for (int u = 0; u < 8; u++)
#pragma unroll
        for (int j = 0; j < 2; j++) {
            part[u][j] += __shfl_down_sync(0xFFFFFFFFu, part[u][j], 16);
            part[u][j] += __shfl_down_sync(0xFFFFFFFFu, part[u][j], 8);
            part[u][j] += __shfl_down_sync(0xFFFFFFFFu, part[u][j], 4);
        }
    if (lane < 4) {
#pragma unroll
        for (int u = 0; u < 8; u++)
#pragma unroll
            for (int j = 0; j < 2; j++)
                red[warp_m][warp_n * 64 + u * 8 + ti * 2 + j] = part[u][j];
    }
    __syncthreads();
    if (tid < 128) {
        float s = red[0][tid] + red[1][tid] + red[2][tid] + red[3][tid];
        g_epart[pz][b * HW + pixbase + tid] = s;
    }
}

// ================= softmax pass 1 (launch 2) =================
__global__ void softmax1_kernel(const float* __restrict__ vab) {
    const int b = blockIdx.y, tile = blockIdx.x, tid = threadIdx.x;
    const int idx = b * HW + tile * 128 + tid;
    float v = expf(g_epart[0][idx] + g_epart[1][idx] +
                   g_epart[2][idx] + g_epart[3][idx] + vab[0]);
    g_e[idx] = v;
#pragma unroll
    for (int o = 16; o > 0; o >>= 1) v += __shfl_down_sync(0xFFFFFFFFu, v, o);
    __shared__ float red[4];
    if ((tid & 31) == 0) red[tid >> 5] = v;
    __syncthreads();
    if (tid == 0) g_ps[b * 32 + tile] = red[0] + red[1] + red[2] + red[3];
}

// ================= fused outputs (launch 3 — profiled) =================
// Each block recomputes S from the 32 partials (deterministic fixed order).
#define CTX_BLOCKS (BS * CDIM)
__global__ void outputs_kernel(float* __restrict__ out_ctx, float* __restrict__ out_alpha) {
    const int bx = blockIdx.x, tid = threadIdx.x;
    const int b = (bx < CTX_BLOCKS) ? (bx / CDIM)
                                    : (((bx - CTX_BLOCKS) * 128) >> 12);
    __shared__ float Ssh;
    if (tid == 0) {
        float s = 0.f;
        const float* ps = g_ps + b * 32;
#pragma unroll
        for (int i = 0; i < 32; i++) s += ps[i];
        Ssh = s + 1e-8f;
    }
    __syncthreads();
    const float S = Ssh;

    if (bx < CTX_BLOCKS) {
        const int c = bx - b * CDIM;
        const __half2* xr = (const __half2*)(g_Bh + ((size_t)b * KPAD + c) * HW);
        const float* er = g_e + b * HW;
        float s = 0.f;
        for (int i = tid; i < HW / 2; i += 128) {
            float2 xv = __half22float2(xr[i]);
            s = fmaf(xv.x, er[2 * i], s);
            s = fmaf(xv.y, er[2 * i + 1], s);
        }
        __shared__ float red[128];
        red[tid] = s;
        __syncthreads();
        for (int st = 64; st > 0; st >>= 1) {
            if (tid < st) red[tid] += red[tid + st];
            __syncthreads();
        }
        if (tid == 0) out_ctx[bx] = red[0] / S;
    } else {
        const int base = (bx - CTX_BLOCKS) * 128 + tid;
        if (base < BS * HW) out_alpha[base] = g_e[base] / S;
    }
}

// ================= launch =================
extern "C" void kernel_launch(void* const* d_in, const int* in_sizes, int n_in,
                              void* d_out, int out_size) {
    const float* x        = (const float*)d_in[0];
    const float* st_hat   = (const float*)d_in[1];
    const float* alpha    = (const float*)d_in[2];
    const float* convQ_w  = (const float*)d_in[3];
    const float* convQ_b  = (const float*)d_in[4];
    const float* Wa_w     = (const float*)d_in[5];
    const float* Wa_b     = (const float*)d_in[6];
    const float* convUa_w = (const float*)d_in[7];
    const float* convUa_b = (const float*)d_in[8];
    const float* Uf_w     = (const float*)d_in[9];
    const float* Uf_b     = (const float*)d_in[10];
    const float* Va_w     = (const float*)d_in[11];
    const float* Va_b     = (const float*)d_in[12];

    float* out_ctx   = (float*)d_out;
    float* out_alpha = (float*)d_out + BS * CDIM;

    const int dyn_bytes = NSTAGES * STAGE_B;   // 75776
    cudaFuncSetAttribute(score_kernel, cudaFuncAttributeMaxDynamicSharedMemorySize,
                         dyn_bytes);

    {   // launch 0: fused prep (g_Bh + g_Ah + g_qe)
        dim3 g(PREP_GX, BS);
        prep_kernel<<<g, 256>>>(x, alpha, convUa_w, Uf_w, convQ_w,
                                st_hat, Wa_w, Wa_b, convUa_b, Uf_b, convQ_b);
    }
    {   // launch 1: score, x = (tile<<2)|pz
        dim3 gs(128, BS);
        score_kernel<<<gs, 256, dyn_bytes>>>(Va_w);
    }
    {   // launch 2
        dim3 g(32, BS);
        softmax1_kernel<<<g, 128>>>(Va_b);
    }
    // launch 3 (profiled): fused context + alpha outputs
    outputs_kernel<<<CTX_BLOCKS + 512, 128>>>(out_ctx, out_alpha);
}